// round 14
// baseline (speedup 1.0000x reference)
#include <cuda_runtime.h>
#include <cuda_fp16.h>
#include <cstdint>

// ---------------------------------------------------------------------------
// Problem constants
// ---------------------------------------------------------------------------
#define IMGS 24          // B*T
#define HWDIM 56
#define WSZ 7
#define NWIN (IMGS*64)          // 1536
#define NTOK 49
#define M_TOTAL (NWIN*NTOK)     // 75264
#define DMODEL 384
#define NHEAD 12
#define HD 32
#define QKV_N 1152
#define BKH 64                  // halves per k-chunk
#define STAGES 3
#define ROWSTR 72               // halves per smem row (144B; conflict-free LDSM)
#define TILE_B (128*ROWSTR*2)   // 18432 B: 128 rows x 64h
#define STG_B (TILE_B*2)        // 36864 B per stage (A + B)

// ---------------------------------------------------------------------------
// Scratch (device globals; allocation is forbidden)
// ---------------------------------------------------------------------------
__device__ __half g_xw [M_TOTAL * DMODEL];     // LN'd, windowed, fp16
__device__ __half g_qkv[M_TOTAL * QKV_N];      // qkv projection, fp16
__device__ __half g_att[M_TOTAL * DMODEL];     // attention out, fp16
__device__ __half g_wqt[QKV_N * DMODEL];       // qkv_w transposed [N][K], fp16
__device__ __half g_wpt[DMODEL * DMODEL];      // proj_w transposed [N][K], fp16
__device__ float  g_biasx[NHEAD * NTOK * 56];  // expanded rel bias (cols 49..55 = -1e30)

// ---------------------------------------------------------------------------
// Helpers
// ---------------------------------------------------------------------------
__device__ __forceinline__ void cp16(uint32_t dst, const void* src) {
    asm volatile("cp.async.cg.shared.global [%0], [%1], 16;\n" :: "r"(dst), "l"(src));
}

// exp(x) on the FMA pipe.  rel err ~2e-6.
__device__ __forceinline__ float fast_exp(float x) {
    const float LOG2E = 1.4426950408889634f;
    float y0 = x * LOG2E;
    float t  = __fadd_rn(y0, 12582912.0f);
    int   n  = __float_as_int(t) - 0x4B400000;
    float fn = __fadd_rn(t, -12582912.0f);
    float f  = y0 - fn;
    float p  = 1.3333558e-3f;
    p = fmaf(p, f, 9.6181293e-3f);
    p = fmaf(p, f, 5.5504109e-2f);
    p = fmaf(p, f, 2.4022651e-1f);
    p = fmaf(p, f, 6.9314718e-1f);
    p = fmaf(p, f, 1.0f);
    n = max(n, -126);
    float s = __int_as_float((n + 127) << 23);
    return s * p;
}

#define MMA_F16(C, A, B)                                                      \
    asm volatile(                                                             \
        "mma.sync.aligned.m16n8k16.row.col.f32.f16.f16.f32 "                  \
        "{%0,%1,%2,%3}, {%4,%5,%6,%7}, {%8,%9}, {%0,%1,%2,%3};\n"             \
        : "+f"((C)[0]), "+f"((C)[1]), "+f"((C)[2]), "+f"((C)[3])              \
        : "r"((A)[0]), "r"((A)[1]), "r"((A)[2]), "r"((A)[3]),                 \
          "r"((B)[0]), "r"((B)[1]))

#define LDSM4(R0, R1, R2, R3, addr)                                           \
    asm volatile("ldmatrix.sync.aligned.m8n8.x4.shared.b16 {%0,%1,%2,%3}, [%4];" \
        : "=r"(R0), "=r"(R1), "=r"(R2), "=r"(R3) : "r"(addr))

#define LDSM4T(R0, R1, R2, R3, addr)                                          \
    asm volatile("ldmatrix.sync.aligned.m8n8.x4.trans.shared.b16 {%0,%1,%2,%3}, [%4];" \
        : "=r"(R0), "=r"(R1), "=r"(R2), "=r"(R3) : "r"(addr))

// ---------------------------------------------------------------------------
// Kernel 0: weight transposes + bias expansion (single launch)
// ---------------------------------------------------------------------------
__global__ void prep_kernel(const float* __restrict__ wq, __half* __restrict__ wqt,
                            const float* __restrict__ wp, __half* __restrict__ wpt,
                            const float* __restrict__ relb, float* __restrict__ biasx)
{
    int i = blockIdx.x * 256 + threadIdx.x;
    const int NQ = QKV_N * DMODEL;
    const int NP = DMODEL * DMODEL;
    if (i < NQ) {
        int n = i / DMODEL, k = i - n * DMODEL;
        wqt[i] = __float2half_rn(wq[(size_t)k * QKV_N + n]);
    } else if (i < NQ + NP) {
        int j = i - NQ;
        int n = j / DMODEL, k = j - n * DMODEL;
        wpt[j] = __float2half_rn(wp[(size_t)k * DMODEL + n]);
    } else if (i < NQ + NP + NHEAD * NTOK * 56) {
        int j = i - NQ - NP;
        int head = j / (NTOK * 56);
        int rc = j - head * NTOK * 56;
        int r = rc / 56, col = rc - r * 56;
        float v = -1e30f;
        if (col < NTOK) {
            int iy = r / WSZ, ix = r - iy * WSZ;
            int jy = col / WSZ, jx = col - jy * WSZ;
            v = relb[((iy - jy + 6) * 13 + (ix - jx + 6)) * NHEAD + head];
        }
        biasx[j] = v;
    }
}

// ---------------------------------------------------------------------------
// Kernel 1: LayerNorm + window partition, one WARP per token (no smem/bar).
// ---------------------------------------------------------------------------
__global__ __launch_bounds__(256)
void ln_window_kernel(const float* __restrict__ x, const float* __restrict__ g,
                      const float* __restrict__ b, __half* __restrict__ xw)
{
    int warp = threadIdx.x >> 5, lane = threadIdx.x & 31;
    int m = blockIdx.x * 8 + warp;
    int win = m / NTOK, n = m - win * NTOK;
    int img = win >> 6;
    int wy  = (win >> 3) & 7;
    int wx  = win & 7;
    int iy = n / WSZ, ix = n - iy * WSZ;
    int h = wy * WSZ + iy;
    int w = wx * WSZ + ix;
    const float* xin = x + ((size_t)(img * HWDIM + h) * HWDIM + w) * DMODEL;

    float4 v[3];
    #pragma unroll
    for (int i = 0; i < 3; i++) v[i] = ((const float4*)xin)[lane + 32 * i];
    float s = 0.f, ss = 0.f;
    #pragma unroll
    for (int i = 0; i < 3; i++) {
        s  += v[i].x + v[i].y + v[i].z + v[i].w;
        ss += v[i].x*v[i].x + v[i].y*v[i].y + v[i].z*v[i].z + v[i].w*v[i].w;
    }
    #pragma unroll
    for (int off = 16; off; off >>= 1) {
        s  += __shfl_xor_sync(0xffffffffu, s,  off);
        ss += __shfl_xor_sync(0xffffffffu, ss, off);
    }
    float mu  = s * (1.f / DMODEL);
    float var = ss * (1.f / DMODEL) - mu * mu;
    float rstd = rsqrtf(var + 1e-5f);

    __half* orow = xw + (size_t)m * DMODEL;
    #pragma unroll
    for (int i = 0; i < 3; i++) {
        float4 gg = ((const float4*)g)[lane + 32 * i];
        float4 bb = ((const float4*)b)[lane + 32 * i];
        __half2 h0 = __floats2half2_rn((v[i].x - mu) * rstd * gg.x + bb.x,
                                       (v[i].y - mu) * rstd * gg.y + bb.y);
        __half2 h1 = __floats2half2_rn((v[i].z - mu) * rstd * gg.z + bb.z,
                                       (v[i].w - mu) * rstd * gg.w + bb.w);
        uint2 o;
        o.x = *(uint32_t*)&h0;
        o.y = *(uint32_t*)&h1;
        ((uint2*)orow)[lane + 32 * i] = o;
    }
}

// ---------------------------------------------------------------------------
// fp16 tensor-core GEMM (unchanged from R12): 128x128 CTA, 8 warps, BKH=64.
// ---------------------------------------------------------------------------
template<int NC, int MODE>
__global__ __launch_bounds__(256, 2)
void mma_gemm(const __half* __restrict__ A, const __half* __restrict__ Wt,
              const float* __restrict__ bias, void* __restrict__ Cout)
{
    extern __shared__ __half smem[];
    const uint32_t sbase = (uint32_t)__cvta_generic_to_shared(smem);

    const int tid   = threadIdx.x;
    const int lane  = tid & 31;
    const int warp  = tid >> 5;
    const int mwarp = warp >> 1;
    const int nwarp = warp & 1;
    const int m0 = blockIdx.y * 128;
    const int n0 = blockIdx.x * 128;

    float c[2][8][4];
    #pragma unroll
    for (int i = 0; i < 2; i++)
        #pragma unroll
        for (int j = 0; j < 8; j++)
            #pragma unroll
            for (int q = 0; q < 4; q++) c[i][j][q] = 0.f;

    auto load_stage = [&](int kt, int buf) {
        int k0 = kt * BKH;
        #pragma unroll
        for (int i = 0; i < 4; i++) {
            int idx = tid + i * 256;
            int row = idx >> 3, q = idx & 7;
            cp16(sbase + buf * STG_B + (row * ROWSTR + q * 8) * 2,
                 A + (size_t)(m0 + row) * DMODEL + k0 + q * 8);
        }
        #pragma unroll
        for (int i = 0; i < 4; i++) {
            int idx = tid + i * 256;
            int row = idx >> 3, q = idx & 7;
            cp16(sbase + buf * STG_B + TILE_B + (row * ROWSTR + q * 8) * 2,
                 Wt + (size_t)(n0 + row) * DMODEL + k0 + q * 8);
        }
        asm volatile("cp.async.commit_group;\n");
    };

    const int KT = DMODEL / BKH;   // 6
    load_stage(0, 0);
    load_stage(1, 1);

    for (int kt = 0; kt < KT; kt++) {
        int buf = kt % STAGES;
        if (kt + 1 < KT) {
            asm volatile("cp.async.wait_group 1;\n" ::: "memory");
        } else {
            asm volatile("cp.async.wait_group 0;\n" ::: "memory");
        }
        __syncthreads();
        if (kt + 2 < KT)
            load_stage(kt + 2, (kt + 2) % STAGES);

        #pragma unroll
        for (int ks = 0; ks < 4; ks++) {
            uint32_t a[2][4], rb[4][4];
            #pragma unroll
            for (int mt = 0; mt < 2; mt++) {
                int row = mwarp * 32 + mt * 16 + ((lane >> 3) & 1) * 8 + (lane & 7);
                uint32_t addr = sbase + buf * STG_B + row * (ROWSTR * 2) + ks * 32 + (lane >> 4) * 16;
                LDSM4(a[mt][0], a[mt][1], a[mt][2], a[mt][3], addr);
            }
            #pragma unroll
            for (int j = 0; j < 4; j++) {
                int nrow = nwarp * 64 + j * 16 + (lane >> 4) * 8 + (lane & 7);
                uint32_t addr = sbase + buf * STG_B + TILE_B + nrow * (ROWSTR * 2) + ks * 32 + ((lane >> 3) & 1) * 16;
                LDSM4(rb[j][0], rb[j][1], rb[j][2], rb[j][3], addr);
            }
            #pragma unroll
            for (int mt = 0; mt < 2; mt++)
                #pragma unroll
                for (int nt = 0; nt < 8; nt++) {
                    uint32_t bfr[2] = { rb[nt >> 1][(nt & 1) * 2],
                                        rb[nt >> 1][(nt & 1) * 2 + 1] };
                    MMA_F16(c[mt][nt], a[mt], bfr);
                }
        }
    }

    #pragma unroll
    for (int mt = 0; mt < 2; mt++) {
        #pragma unroll
        for (int half = 0; half < 2; half++) {
            int m = m0 + mwarp * 32 + mt * 16 + (lane >> 2) + half * 8;
            #pragma unroll
            for (int nt = 0; nt < 8; nt++) {
                int col = n0 + nwarp * 64 + nt * 8 + 2 * (lane & 3);
                float vx = c[mt][nt][half * 2 + 0] + __ldg(&bias[col]);
                float vy = c[mt][nt][half * 2 + 1] + __ldg(&bias[col + 1]);
                if (MODE == 0) {
                    __half* op = (__half*)Cout + (size_t)m * NC;
                    __half2 hv = __floats2half2_rn(vx, vy);
                    *(__half2*)(op + col) = hv;
                } else {
                    int win = m / NTOK, n = m - win * NTOK;
                    int img = win >> 6;
                    int wy = (win >> 3) & 7;
                    int wx = win & 7;
                    int iy = n / WSZ, ix = n - iy * WSZ;
                    int ro = (img * HWDIM + wy * WSZ + iy) * HWDIM + wx * WSZ + ix;
                    float* op = (float*)Cout + (size_t)ro * DMODEL;
                    float2 v; v.x = vx; v.y = vy;
                    *(float2*)(op + col) = v;
                }
            }
        }
    }
}

// ---------------------------------------------------------------------------
// Kernel 3: fp16 tensor-core windowed attention, TWO heads per 256-thr block,
// all MMA fragments fed by ldmatrix (no scalar LDS in the hot path).
// ---------------------------------------------------------------------------
__global__ __launch_bounds__(256)
void attn_mma_kernel(const __half* __restrict__ qkv, const float* __restrict__ biasx,
                     __half* __restrict__ attout)
{
    __shared__ __half qs[2][64 * 40];   // rows 49..63 garbage (row-confined)
    __shared__ __half ks[2][64 * 40];   // rows 49..63 zeroed
    __shared__ __half vs[2][64 * 40];   // rows 49..63 zeroed
    __shared__ __half Ps[2][64 * 72];   // P; cols 56..63 zeroed

    const int blk  = blockIdx.x;
    const int win  = blk / 6;
    const int hp   = blk - win * 6;
    const int tid  = threadIdx.x;
    const int lane = tid & 31;
    const int warp = tid >> 5;
    const int hh   = warp >> 2;          // 0/1: which head this warp works on
    const int wl   = warp & 3;           // warp-in-head
    const int head = hp * 2 + hh;
    const float scale = 0.17677669529663687f;

    // zero pads, both heads: per head ks 75 + vs 75 + Ps 64 = 214 items
    for (int idx = tid; idx < 2 * 214; idx += 256) {
        int h2 = idx & 1, j = idx >> 1;
        uint4 z = make_uint4(0, 0, 0, 0);
        if (j < 75) {
            int r = 49 + j / 5, q = j % 5;
            *(uint4*)&ks[h2][r * 40 + q * 8] = z;
        } else if (j < 150) {
            int jj = j - 75;
            int r = 49 + jj / 5, q = jj % 5;
            *(uint4*)&vs[h2][r * 40 + q * 8] = z;
        } else {
            int r = j - 150;
            *(uint4*)&Ps[h2][r * 72 + 56] = z;
        }
    }

    const size_t base0 = (size_t)win * NTOK * QKV_N + (hp * 2) * HD;

    // load q, k, v for both heads (uint4 vector copies)
    for (int idx = tid; idx < 2 * NTOK * 4; idx += 256) {
        int h2 = idx & 1, item = idx >> 1;
        int n = item >> 2, cq = item & 3;
        const __half* p = qkv + base0 + h2 * HD + (size_t)n * QKV_N + cq * 8;
        *(uint4*)&qs[h2][n * 40 + cq * 8] = *(const uint4*)(p);
        *(uint4*)&ks[h2][n * 40 + cq * 8] = *(const uint4*)(p + DMODEL);
        *(uint4*)&vs[h2][n * 40 + cq * 8] = *(const uint4*)(p + 2 * DMODEL);
    }
    __syncthreads();

    const uint32_t qsb = (uint32_t)__cvta_generic_to_shared(&qs[hh][0]);
    const uint32_t ksb = (uint32_t)__cvta_generic_to_shared(&ks[hh][0]);
    const uint32_t vsb = (uint32_t)__cvta_generic_to_shared(&vs[hh][0]);
    const uint32_t psb = (uint32_t)__cvta_generic_to_shared(&Ps[hh][0]);

    // ---- S = q @ k^T : each warp 16 rows x 56 cols; LDSM fragments ----
    float cS[7][4];
    #pragma unroll
    for (int nt = 0; nt < 7; nt++)
        #pragma unroll
        for (int q = 0; q < 4; q++) cS[nt][q] = 0.f;

    const int arow = wl * 16 + ((lane >> 3) & 1) * 8 + (lane & 7);   // A-frag row
    #pragma unroll
    for (int kt = 0; kt < 2; kt++) {
        uint32_t a[4], rb[4][4];
        LDSM4(a[0], a[1], a[2], a[3], qsb + arow * 80 + kt * 32 + (lane >> 4) * 16);
        #pragma unroll
        for (int j = 0; j < 4; j++) {
            int nrow = j * 16 + (lane >> 4) * 8 + (lane & 7);
            LDSM4(rb[j][0], rb[j][1], rb[j][2], rb[j][3],
                  ksb + nrow * 80 + kt * 32 + ((lane >> 3) & 1) * 16);
        }
        #pragma unroll
        for (int nt = 0; nt < 7; nt++) {
            uint32_t bfr[2] = { rb[nt >> 1][(nt & 1) * 2],
                                rb[nt >> 1][(nt & 1) * 2 + 1] };
            MMA_F16(cS[nt], a, bfr);
        }
    }

    // ---- scale + bias + softmax per row (bias from expanded table) ----
    const int r0 = wl * 16 + (lane >> 2);
    const int kc = 2 * (lane & 3);
    #pragma unroll
    for (int h = 0; h < 2; h++) {
        int r = r0 + 8 * h;
        bool rvalid = (r < NTOK);
        const float* brow = biasx + ((size_t)head * NTOK + (rvalid ? r : 0)) * 56;
        float vals[14];
        float mx = -1e30f;
        #pragma unroll
        for (int nt = 0; nt < 7; nt++) {
            float2 bb = *(const float2*)(brow + nt * 8 + kc);
            float v0 = rvalid ? fmaf(cS[nt][2 * h + 0], scale, bb.x) : -1e30f;
            float v1 = rvalid ? fmaf(cS[nt][2 * h + 1], scale, bb.y) : -1e30f;
            vals[nt * 2 + 0] = v0;
            vals[nt * 2 + 1] = v1;
            mx = fmaxf(mx, fmaxf(v0, v1));
        }
        mx = fmaxf(mx, __shfl_xor_sync(0xffffffffu, mx, 1));
        mx = fmaxf(mx, __shfl_xor_sync(0xffffffffu, mx, 2));
        float sum = 0.f;
        #pragma unroll
        for (int i = 0; i < 14; i++) {
            float e = fast_exp(vals[i] - mx);
            vals[i] = e;
            sum += e;
        }
        sum += __shfl_xor_sync(0xffffffffu, sum, 1);
        sum += __shfl_xor_sync(0xffffffffu, sum, 2);
        float inv = 1.f / sum;
        #pragma unroll
        for (int nt = 0; nt < 7; nt++) {
            __half2 hv = __floats2half2_rn(vals[nt * 2] * inv, vals[nt * 2 + 1] * inv);
            *(__half2*)&Ps[hh][r * 72 + nt * 8 + kc] = hv;
        }
    }
    __syncwarp();   // Ps rows are warp-private

    // ---- preload V^T fragments via ldmatrix.trans ----
    uint32_t vb[2][4][4];
    {
        int g = lane >> 3, vrow = lane & 7;
        #pragma unroll
        for (int dp = 0; dp < 2; dp++)
            #pragma unroll
            for (int jq = 0; jq < 4; jq++) {
                int j = jq * 16 + (g & 1) * 8 + vrow;
                int d = dp * 16 + (g >> 1) * 8;
                LDSM4T(vb[dp][jq][0], vb[dp][jq][1], vb[dp][jq][2], vb[dp][jq][3],
                       vsb + j * 80 + d * 2);
            }
    }

    // ---- out = P @ V : each warp 16 rows x 32 dims; LDSM A-frags ----
    float o[4][4];
    #pragma unroll
    for (int nt = 0; nt < 4; nt++)
        #pragma unroll
        for (int q = 0; q < 4; q++) o[nt][q] = 0.f;

    #pragma unroll
    for (int kt = 0; kt < 4; kt++) {
        uint32_t a[4];
        LDSM4(a[0], a[1], a[2], a[3], psb + arow * 144 + kt * 32 + (lane >> 4) * 16);
        #pragma unroll
        for (int nt = 0; nt < 4; nt++) {
            uint32_t bfr[2] = { vb[nt >> 1][kt][(nt & 1) * 2],
                                vb[nt >> 1][kt][(nt & 1) * 2 + 1] };
            MMA_F16(o[nt], a, bfr);
        }
    }

    #pragma unroll
    for (int h = 0; h < 2; h++) {
        int r = r0 + 8 * h;
        if (r < NTOK) {
            __half* op = attout + (size_t)(win * NTOK + r) * DMODEL + head * HD;
            #pragma unroll
            for (int nt = 0; nt < 4; nt++) {
                int col = nt * 8 + kc;
                __half2 hv = __floats2half2_rn(o[nt][2 * h + 0], o[nt][2 * h + 1]);
                *(__half2*)(op + col) = hv;
            }
        }
    }
}

// ---------------------------------------------------------------------------
// Launch
// ---------------------------------------------------------------------------
extern "C" void kernel_launch(void* const* d_in, const int* in_sizes, int n_in,
                              void* d_out, int out_size)
{
    const float* x      = (const float*)d_in[0];
    const float* ln_g   = (const float*)d_in[1];
    const float* ln_b   = (const float*)d_in[2];
    const float* qkv_w  = (const float*)d_in[3];
    const float* qkv_b  = (const float*)d_in[4];
    const float* proj_w = (const float*)d_in[5];
    const float* proj_b = (const float*)d_in[6];
    const float* relb   = (const float*)d_in[7];
    float* out = (float*)d_out;

    __half *xw, *qkv, *att, *wqt, *wpt;
    float* biasx;
    cudaGetSymbolAddress((void**)&xw,  g_xw);
    cudaGetSymbolAddress((void**)&qkv, g_qkv);
    cudaGetSymbolAddress((void**)&att, g_att);
    cudaGetSymbolAddress((void**)&wqt, g_wqt);
    cudaGetSymbolAddress((void**)&wpt, g_wpt);
    cudaGetSymbolAddress((void**)&biasx, g_biasx);

    const int gemm_smem = STAGES * STG_B;   // 110592 B
    static int attr_set = 0;
    if (!attr_set) {
        cudaFuncSetAttribute(mma_gemm<QKV_N, 0>,
                             cudaFuncAttributeMaxDynamicSharedMemorySize, gemm_smem);
        cudaFuncSetAttribute(mma_gemm<DMODEL, 1>,
                             cudaFuncAttributeMaxDynamicSharedMemorySize, gemm_smem);
        attr_set = 1;
    }

    const int nprep = QKV_N * DMODEL + DMODEL * DMODEL + NHEAD * NTOK * 56;
    prep_kernel<<<(nprep + 255) / 256, 256>>>(qkv_w, wqt, proj_w, wpt, relb, biasx);
    ln_window_kernel<<<M_TOTAL / 8, 256>>>(x, ln_g, ln_b, xw);
    mma_gemm<QKV_N, 0><<<dim3(QKV_N / 128, M_TOTAL / 128), 256, gemm_smem>>>(xw, wqt, qkv_b, qkv);
    attn_mma_kernel<<<NWIN * 6, 256>>>(qkv, biasx, att);
    mma_gemm<DMODEL, 1><<<dim3(DMODEL / 128, M_TOTAL / 128), 256, gemm_smem>>>(att, wpt, proj_b, out);
}

// round 15
// speedup vs baseline: 1.0204x; 1.0204x over previous
#include <cuda_runtime.h>
#include <cuda_fp16.h>
#include <cstdint>

// ---------------------------------------------------------------------------
// Problem constants
// ---------------------------------------------------------------------------
#define IMGS 24          // B*T
#define HWDIM 56
#define WSZ 7
#define NWIN (IMGS*64)          // 1536
#define NTOK 49
#define M_TOTAL (NWIN*NTOK)     // 75264
#define DMODEL 384
#define NHEAD 12
#define HD 32
#define QKV_N 1152
#define BKH 64                  // halves per k-chunk
#define STAGES 3
#define ROWSTR 72               // halves per smem row (144B; conflict-free LDSM)
#define TILE_B (128*ROWSTR*2)   // 18432 B: 128 rows x 64h
#define STG_B (TILE_B*2)        // 36864 B per stage (A + B)

// ---------------------------------------------------------------------------
// Scratch (device globals; allocation is forbidden)
// ---------------------------------------------------------------------------
__device__ __half g_xw [M_TOTAL * DMODEL];     // LN'd, windowed, fp16
__device__ __half g_qkv[M_TOTAL * QKV_N];      // qkv projection, fp16
__device__ __half g_att[M_TOTAL * DMODEL];     // attention out, fp16
__device__ __half g_wqt[QKV_N * DMODEL];       // qkv_w transposed [N][K], fp16
__device__ __half g_wpt[DMODEL * DMODEL];      // proj_w transposed [N][K], fp16
__device__ float  g_biasx[NHEAD * NTOK * 56];  // expanded rel bias (cols 49..55 = -1e30)

// ---------------------------------------------------------------------------
// Helpers
// ---------------------------------------------------------------------------
__device__ __forceinline__ void cp16(uint32_t dst, const void* src) {
    asm volatile("cp.async.cg.shared.global [%0], [%1], 16;\n" :: "r"(dst), "l"(src));
}

// exp(x) on the FMA pipe.  rel err ~2e-6.
__device__ __forceinline__ float fast_exp(float x) {
    const float LOG2E = 1.4426950408889634f;
    float y0 = x * LOG2E;
    float t  = __fadd_rn(y0, 12582912.0f);
    int   n  = __float_as_int(t) - 0x4B400000;
    float fn = __fadd_rn(t, -12582912.0f);
    float f  = y0 - fn;
    float p  = 1.3333558e-3f;
    p = fmaf(p, f, 9.6181293e-3f);
    p = fmaf(p, f, 5.5504109e-2f);
    p = fmaf(p, f, 2.4022651e-1f);
    p = fmaf(p, f, 6.9314718e-1f);
    p = fmaf(p, f, 1.0f);
    n = max(n, -126);
    float s = __int_as_float((n + 127) << 23);
    return s * p;
}

#define MMA_F16(C, A, B)                                                      \
    asm volatile(                                                             \
        "mma.sync.aligned.m16n8k16.row.col.f32.f16.f16.f32 "                  \
        "{%0,%1,%2,%3}, {%4,%5,%6,%7}, {%8,%9}, {%0,%1,%2,%3};\n"             \
        : "+f"((C)[0]), "+f"((C)[1]), "+f"((C)[2]), "+f"((C)[3])              \
        : "r"((A)[0]), "r"((A)[1]), "r"((A)[2]), "r"((A)[3]),                 \
          "r"((B)[0]), "r"((B)[1]))

#define LDSM4(R0, R1, R2, R3, addr)                                           \
    asm volatile("ldmatrix.sync.aligned.m8n8.x4.shared.b16 {%0,%1,%2,%3}, [%4];" \
        : "=r"(R0), "=r"(R1), "=r"(R2), "=r"(R3) : "r"(addr))

#define LDSM4T(R0, R1, R2, R3, addr)                                          \
    asm volatile("ldmatrix.sync.aligned.m8n8.x4.trans.shared.b16 {%0,%1,%2,%3}, [%4];" \
        : "=r"(R0), "=r"(R1), "=r"(R2), "=r"(R3) : "r"(addr))

// ---------------------------------------------------------------------------
// Kernel 0: weight transposes + bias expansion (single launch)
// ---------------------------------------------------------------------------
__global__ void prep_kernel(const float* __restrict__ wq, __half* __restrict__ wqt,
                            const float* __restrict__ wp, __half* __restrict__ wpt,
                            const float* __restrict__ relb, float* __restrict__ biasx)
{
    int i = blockIdx.x * 256 + threadIdx.x;
    const int NQ = QKV_N * DMODEL;
    const int NP = DMODEL * DMODEL;
    if (i < NQ) {
        int n = i / DMODEL, k = i - n * DMODEL;
        wqt[i] = __float2half_rn(wq[(size_t)k * QKV_N + n]);
    } else if (i < NQ + NP) {
        int j = i - NQ;
        int n = j / DMODEL, k = j - n * DMODEL;
        wpt[j] = __float2half_rn(wp[(size_t)k * DMODEL + n]);
    } else if (i < NQ + NP + NHEAD * NTOK * 56) {
        int j = i - NQ - NP;
        int head = j / (NTOK * 56);
        int rc = j - head * NTOK * 56;
        int r = rc / 56, col = rc - r * 56;
        float v = -1e30f;
        if (col < NTOK) {
            int iy = r / WSZ, ix = r - iy * WSZ;
            int jy = col / WSZ, jx = col - jy * WSZ;
            v = relb[((iy - jy + 6) * 13 + (ix - jx + 6)) * NHEAD + head];
        }
        biasx[j] = v;
    }
}

// ---------------------------------------------------------------------------
// Kernel 1: LayerNorm + window partition, one WARP per token (no smem/bar).
// ---------------------------------------------------------------------------
__global__ __launch_bounds__(256)
void ln_window_kernel(const float* __restrict__ x, const float* __restrict__ g,
                      const float* __restrict__ b, __half* __restrict__ xw)
{
    int warp = threadIdx.x >> 5, lane = threadIdx.x & 31;
    int m = blockIdx.x * 8 + warp;
    int win = m / NTOK, n = m - win * NTOK;
    int img = win >> 6;
    int wy  = (win >> 3) & 7;
    int wx  = win & 7;
    int iy = n / WSZ, ix = n - iy * WSZ;
    int h = wy * WSZ + iy;
    int w = wx * WSZ + ix;
    const float* xin = x + ((size_t)(img * HWDIM + h) * HWDIM + w) * DMODEL;

    float4 v[3];
    #pragma unroll
    for (int i = 0; i < 3; i++) v[i] = ((const float4*)xin)[lane + 32 * i];
    float s = 0.f, ss = 0.f;
    #pragma unroll
    for (int i = 0; i < 3; i++) {
        s  += v[i].x + v[i].y + v[i].z + v[i].w;
        ss += v[i].x*v[i].x + v[i].y*v[i].y + v[i].z*v[i].z + v[i].w*v[i].w;
    }
    #pragma unroll
    for (int off = 16; off; off >>= 1) {
        s  += __shfl_xor_sync(0xffffffffu, s,  off);
        ss += __shfl_xor_sync(0xffffffffu, ss, off);
    }
    float mu  = s * (1.f / DMODEL);
    float var = ss * (1.f / DMODEL) - mu * mu;
    float rstd = rsqrtf(var + 1e-5f);

    __half* orow = xw + (size_t)m * DMODEL;
    #pragma unroll
    for (int i = 0; i < 3; i++) {
        float4 gg = ((const float4*)g)[lane + 32 * i];
        float4 bb = ((const float4*)b)[lane + 32 * i];
        __half2 h0 = __floats2half2_rn((v[i].x - mu) * rstd * gg.x + bb.x,
                                       (v[i].y - mu) * rstd * gg.y + bb.y);
        __half2 h1 = __floats2half2_rn((v[i].z - mu) * rstd * gg.z + bb.z,
                                       (v[i].w - mu) * rstd * gg.w + bb.w);
        uint2 o;
        o.x = *(uint32_t*)&h0;
        o.y = *(uint32_t*)&h1;
        ((uint2*)orow)[lane + 32 * i] = o;
    }
}

// ---------------------------------------------------------------------------
// fp16 tensor-core GEMM (unchanged from R12): 128x128 CTA, 8 warps, BKH=64.
// ---------------------------------------------------------------------------
template<int NC, int MODE>
__global__ __launch_bounds__(256, 2)
void mma_gemm(const __half* __restrict__ A, const __half* __restrict__ Wt,
              const float* __restrict__ bias, void* __restrict__ Cout)
{
    extern __shared__ __half smem[];
    const uint32_t sbase = (uint32_t)__cvta_generic_to_shared(smem);

    const int tid   = threadIdx.x;
    const int lane  = tid & 31;
    const int warp  = tid >> 5;
    const int mwarp = warp >> 1;
    const int nwarp = warp & 1;
    const int m0 = blockIdx.y * 128;
    const int n0 = blockIdx.x * 128;

    float c[2][8][4];
    #pragma unroll
    for (int i = 0; i < 2; i++)
        #pragma unroll
        for (int j = 0; j < 8; j++)
            #pragma unroll
            for (int q = 0; q < 4; q++) c[i][j][q] = 0.f;

    auto load_stage = [&](int kt, int buf) {
        int k0 = kt * BKH;
        #pragma unroll
        for (int i = 0; i < 4; i++) {
            int idx = tid + i * 256;
            int row = idx >> 3, q = idx & 7;
            cp16(sbase + buf * STG_B + (row * ROWSTR + q * 8) * 2,
                 A + (size_t)(m0 + row) * DMODEL + k0 + q * 8);
        }
        #pragma unroll
        for (int i = 0; i < 4; i++) {
            int idx = tid + i * 256;
            int row = idx >> 3, q = idx & 7;
            cp16(sbase + buf * STG_B + TILE_B + (row * ROWSTR + q * 8) * 2,
                 Wt + (size_t)(n0 + row) * DMODEL + k0 + q * 8);
        }
        asm volatile("cp.async.commit_group;\n");
    };

    const int KT = DMODEL / BKH;   // 6
    load_stage(0, 0);
    load_stage(1, 1);

    for (int kt = 0; kt < KT; kt++) {
        int buf = kt % STAGES;
        if (kt + 1 < KT) {
            asm volatile("cp.async.wait_group 1;\n" ::: "memory");
        } else {
            asm volatile("cp.async.wait_group 0;\n" ::: "memory");
        }
        __syncthreads();
        if (kt + 2 < KT)
            load_stage(kt + 2, (kt + 2) % STAGES);

        #pragma unroll
        for (int ks = 0; ks < 4; ks++) {
            uint32_t a[2][4], rb[4][4];
            #pragma unroll
            for (int mt = 0; mt < 2; mt++) {
                int row = mwarp * 32 + mt * 16 + ((lane >> 3) & 1) * 8 + (lane & 7);
                uint32_t addr = sbase + buf * STG_B + row * (ROWSTR * 2) + ks * 32 + (lane >> 4) * 16;
                LDSM4(a[mt][0], a[mt][1], a[mt][2], a[mt][3], addr);
            }
            #pragma unroll
            for (int j = 0; j < 4; j++) {
                int nrow = nwarp * 64 + j * 16 + (lane >> 4) * 8 + (lane & 7);
                uint32_t addr = sbase + buf * STG_B + TILE_B + nrow * (ROWSTR * 2) + ks * 32 + ((lane >> 3) & 1) * 16;
                LDSM4(rb[j][0], rb[j][1], rb[j][2], rb[j][3], addr);
            }
            #pragma unroll
            for (int mt = 0; mt < 2; mt++)
                #pragma unroll
                for (int nt = 0; nt < 8; nt++) {
                    uint32_t bfr[2] = { rb[nt >> 1][(nt & 1) * 2],
                                        rb[nt >> 1][(nt & 1) * 2 + 1] };
                    MMA_F16(c[mt][nt], a[mt], bfr);
                }
        }
    }

    #pragma unroll
    for (int mt = 0; mt < 2; mt++) {
        #pragma unroll
        for (int half = 0; half < 2; half++) {
            int m = m0 + mwarp * 32 + mt * 16 + (lane >> 2) + half * 8;
            #pragma unroll
            for (int nt = 0; nt < 8; nt++) {
                int col = n0 + nwarp * 64 + nt * 8 + 2 * (lane & 3);
                float vx = c[mt][nt][half * 2 + 0] + __ldg(&bias[col]);
                float vy = c[mt][nt][half * 2 + 1] + __ldg(&bias[col + 1]);
                if (MODE == 0) {
                    __half* op = (__half*)Cout + (size_t)m * NC;
                    __half2 hv = __floats2half2_rn(vx, vy);
                    *(__half2*)(op + col) = hv;
                } else {
                    int win = m / NTOK, n = m - win * NTOK;
                    int img = win >> 6;
                    int wy = (win >> 3) & 7;
                    int wx = win & 7;
                    int iy = n / WSZ, ix = n - iy * WSZ;
                    int ro = (img * HWDIM + wy * WSZ + iy) * HWDIM + wx * WSZ + ix;
                    float* op = (float*)Cout + (size_t)ro * DMODEL;
                    float2 v; v.x = vx; v.y = vy;
                    *(float2*)(op + col) = v;
                }
            }
        }
    }
}

// ---------------------------------------------------------------------------
// Kernel 3: fp16 windowed attention, TWO heads per 256-thr block.
// P is kept in REGISTERS: the S C-fragment layout equals the P@V A-fragment
// layout, so softmax packs half2 probabilities directly into A-frags.
// No P smem round-trip at all.
// ---------------------------------------------------------------------------
__global__ __launch_bounds__(256)
void attn_mma_kernel(const __half* __restrict__ qkv, const float* __restrict__ biasx,
                     __half* __restrict__ attout)
{
    __shared__ __half qs[2][64 * 40];   // rows 49..63 garbage (row-confined)
    __shared__ __half ks[2][64 * 40];   // rows 49..63 zeroed
    __shared__ __half vs[2][64 * 40];   // rows 49..63 zeroed

    const int blk  = blockIdx.x;
    const int win  = blk / 6;
    const int hp   = blk - win * 6;
    const int tid  = threadIdx.x;
    const int lane = tid & 31;
    const int warp = tid >> 5;
    const int hh   = warp >> 2;          // 0/1: which head this warp works on
    const int wl   = warp & 3;           // warp-in-head
    const int head = hp * 2 + hh;
    const float scale = 0.17677669529663687f;

    // zero pads, both heads: per head ks 75 + vs 75 = 150 items
    for (int idx = tid; idx < 2 * 150; idx += 256) {
        int h2 = idx & 1, j = idx >> 1;
        uint4 z = make_uint4(0, 0, 0, 0);
        if (j < 75) {
            int r = 49 + j / 5, q = j % 5;
            *(uint4*)&ks[h2][r * 40 + q * 8] = z;
        } else {
            int jj = j - 75;
            int r = 49 + jj / 5, q = jj % 5;
            *(uint4*)&vs[h2][r * 40 + q * 8] = z;
        }
    }

    const size_t base0 = (size_t)win * NTOK * QKV_N + (hp * 2) * HD;

    // load q, k, v for both heads (uint4 vector copies)
    for (int idx = tid; idx < 2 * NTOK * 4; idx += 256) {
        int h2 = idx & 1, item = idx >> 1;
        int n = item >> 2, cq = item & 3;
        const __half* p = qkv + base0 + h2 * HD + (size_t)n * QKV_N + cq * 8;
        *(uint4*)&qs[h2][n * 40 + cq * 8] = *(const uint4*)(p);
        *(uint4*)&ks[h2][n * 40 + cq * 8] = *(const uint4*)(p + DMODEL);
        *(uint4*)&vs[h2][n * 40 + cq * 8] = *(const uint4*)(p + 2 * DMODEL);
    }
    __syncthreads();

    const uint32_t qsb = (uint32_t)__cvta_generic_to_shared(&qs[hh][0]);
    const uint32_t ksb = (uint32_t)__cvta_generic_to_shared(&ks[hh][0]);
    const uint32_t vsb = (uint32_t)__cvta_generic_to_shared(&vs[hh][0]);

    // ---- S = q @ k^T : each warp 16 rows x 56 cols; LDSM fragments ----
    float cS[7][4];
    #pragma unroll
    for (int nt = 0; nt < 7; nt++)
        #pragma unroll
        for (int q = 0; q < 4; q++) cS[nt][q] = 0.f;

    const int arow = wl * 16 + ((lane >> 3) & 1) * 8 + (lane & 7);   // A-frag row
    #pragma unroll
    for (int kt = 0; kt < 2; kt++) {
        uint32_t a[4], rb[4][4];
        LDSM4(a[0], a[1], a[2], a[3], qsb + arow * 80 + kt * 32 + (lane >> 4) * 16);
        #pragma unroll
        for (int j = 0; j < 4; j++) {
            int nrow = j * 16 + (lane >> 4) * 8 + (lane & 7);
            LDSM4(rb[j][0], rb[j][1], rb[j][2], rb[j][3],
                  ksb + nrow * 80 + kt * 32 + ((lane >> 3) & 1) * 16);
        }
        #pragma unroll
        for (int nt = 0; nt < 7; nt++) {
            uint32_t bfr[2] = { rb[nt >> 1][(nt & 1) * 2],
                                rb[nt >> 1][(nt & 1) * 2 + 1] };
            MMA_F16(cS[nt], a, bfr);
        }
    }

    // ---- scale + bias + softmax; pack P into A-fragment registers ----
    const int r0 = wl * 16 + (lane >> 2);
    const int kc = 2 * (lane & 3);
    uint32_t ph[2][7];                   // ph[h][tile]: half2 P pair
    #pragma unroll
    for (int h = 0; h < 2; h++) {
        int r = r0 + 8 * h;
        bool rvalid = (r < NTOK);
        const float* brow = biasx + ((size_t)head * NTOK + (rvalid ? r : 0)) * 56;
        float vals[14];
        float mx = -1e30f;
        #pragma unroll
        for (int nt = 0; nt < 7; nt++) {
            float2 bb = *(const float2*)(brow + nt * 8 + kc);
            float v0 = rvalid ? fmaf(cS[nt][2 * h + 0], scale, bb.x) : -1e30f;
            float v1 = rvalid ? fmaf(cS[nt][2 * h + 1], scale, bb.y) : -1e30f;
            vals[nt * 2 + 0] = v0;
            vals[nt * 2 + 1] = v1;
            mx = fmaxf(mx, fmaxf(v0, v1));
        }
        mx = fmaxf(mx, __shfl_xor_sync(0xffffffffu, mx, 1));
        mx = fmaxf(mx, __shfl_xor_sync(0xffffffffu, mx, 2));
        float sum = 0.f;
        #pragma unroll
        for (int i = 0; i < 14; i++) {
            float e = fast_exp(vals[i] - mx);
            vals[i] = e;
            sum += e;
        }
        sum += __shfl_xor_sync(0xffffffffu, sum, 1);
        sum += __shfl_xor_sync(0xffffffffu, sum, 2);
        float inv = 1.f / sum;
        #pragma unroll
        for (int nt = 0; nt < 7; nt++) {
            __half2 hv = __floats2half2_rn(vals[nt * 2] * inv, vals[nt * 2 + 1] * inv);
            ph[h][nt] = *(uint32_t*)&hv;
        }
    }

    // ---- preload V^T fragments via ldmatrix.trans ----
    uint32_t vb[2][4][4];
    {
        int g = lane >> 3, vrow = lane & 7;
        #pragma unroll
        for (int dp = 0; dp < 2; dp++)
            #pragma unroll
            for (int jq = 0; jq < 4; jq++) {
                int j = jq * 16 + (g & 1) * 8 + vrow;
                int d = dp * 16 + (g >> 1) * 8;
                LDSM4T(vb[dp][jq][0], vb[dp][jq][1], vb[dp][jq][2], vb[dp][jq][3],
                       vsb + j * 80 + d * 2);
            }
    }

    // ---- out = P @ V : A-frags straight from ph registers (no smem) ----
    float o[4][4];
    #pragma unroll
    for (int nt = 0; nt < 4; nt++)
        #pragma unroll
        for (int q = 0; q < 4; q++) o[nt][q] = 0.f;

    #pragma unroll
    for (int kt = 0; kt < 4; kt++) {
        uint32_t a[4];
        a[0] = ph[0][2 * kt];
        a[1] = ph[1][2 * kt];
        a[2] = (kt < 3) ? ph[0][2 * kt + 1] : 0u;
        a[3] = (kt < 3) ? ph[1][2 * kt + 1] : 0u;
        #pragma unroll
        for (int nt = 0; nt < 4; nt++) {
            uint32_t bfr[2] = { vb[nt >> 1][kt][(nt & 1) * 2],
                                vb[nt >> 1][kt][(nt & 1) * 2 + 1] };
            MMA_F16(o[nt], a, bfr);
        }
    }

    #pragma unroll
    for (int h = 0; h < 2; h++) {
        int r = r0 + 8 * h;
        if (r < NTOK) {
            __half* op = attout + (size_t)(win * NTOK + r) * DMODEL + head * HD;
            #pragma unroll
            for (int nt = 0; nt < 4; nt++) {
                int col = nt * 8 + kc;
                __half2 hv = __floats2half2_rn(o[nt][2 * h + 0], o[nt][2 * h + 1]);
                *(__half2*)(op + col) = hv;
            }
        }
    }
}

// ---------------------------------------------------------------------------
// Launch
// ---------------------------------------------------------------------------
extern "C" void kernel_launch(void* const* d_in, const int* in_sizes, int n_in,
                              void* d_out, int out_size)
{
    const float* x      = (const float*)d_in[0];
    const float* ln_g   = (const float*)d_in[1];
    const float* ln_b   = (const float*)d_in[2];
    const float* qkv_w  = (const float*)d_in[3];
    const float* qkv_b  = (const float*)d_in[4];
    const float* proj_w = (const float*)d_in[5];
    const float* proj_b = (const float*)d_in[6];
    const float* relb   = (const float*)d_in[7];
    float* out = (float*)d_out;

    __half *xw, *qkv, *att, *wqt, *wpt;
    float* biasx;
    cudaGetSymbolAddress((void**)&xw,  g_xw);
    cudaGetSymbolAddress((void**)&qkv, g_qkv);
    cudaGetSymbolAddress((void**)&att, g_att);
    cudaGetSymbolAddress((void**)&wqt, g_wqt);
    cudaGetSymbolAddress((void**)&wpt, g_wpt);
    cudaGetSymbolAddress((void**)&biasx, g_biasx);

    const int gemm_smem = STAGES * STG_B;   // 110592 B
    static int attr_set = 0;
    if (!attr_set) {
        cudaFuncSetAttribute(mma_gemm<QKV_N, 0>,
                             cudaFuncAttributeMaxDynamicSharedMemorySize, gemm_smem);
        cudaFuncSetAttribute(mma_gemm<DMODEL, 1>,
                             cudaFuncAttributeMaxDynamicSharedMemorySize, gemm_smem);
        attr_set = 1;
    }

    const int nprep = QKV_N * DMODEL + DMODEL * DMODEL + NHEAD * NTOK * 56;
    prep_kernel<<<(nprep + 255) / 256, 256>>>(qkv_w, wqt, proj_w, wpt, relb, biasx);
    ln_window_kernel<<<M_TOTAL / 8, 256>>>(x, ln_g, ln_b, xw);
    mma_gemm<QKV_N, 0><<<dim3(QKV_N / 128, M_TOTAL / 128), 256, gemm_smem>>>(xw, wqt, qkv_b, qkv);
    attn_mma_kernel<<<NWIN * 6, 256>>>(qkv, biasx, att);
    mma_gemm<DMODEL, 1><<<dim3(DMODEL / 128, M_TOTAL / 128), 256, gemm_smem>>>(att, wpt, proj_b, out);
}